// round 15
// baseline (speedup 1.0000x reference)
#include <cuda_runtime.h>
#include <cstdint>

#define NBLK    128
#define FEAT    32
#define THREADS 256           // 8 warps; warp w owns rows [16w, 16w+16)
#define NBATCH  1024

#define NCHUNK   8            // k-chunks of 16 (one m16n8k16 step each)
#define CHUNK_K  16
#define AW_FLOATS 256         // 16 rows x 16 floats per warp per stage, XOR-swizzled
#define NSTAGE   3
#define NWARPS   8
#define A_BYTES  (NWARPS * NSTAGE * AW_FLOATS * 4)   // 24576
#define BSTRIDE_U32 132       // u32 per B row: 64 hi pairs + 64 lo pairs + 4 pad
#define B_BYTES  (32 * BSTRIDE_U32 * 4)              // 16896
#define SMEM_BYTES (A_BYTES + B_BYTES)               // 41472 -> 4 CTAs/SM (smem), 32 warps/SM

// m16n8k16 bf16 mma: D += A*B, fp32 accumulate.
__device__ __forceinline__ void mma_bf16(float* d, uint32_t a0, uint32_t a1,
                                         uint32_t a2, uint32_t a3,
                                         uint32_t b0, uint32_t b1) {
    asm("mma.sync.aligned.m16n8k16.row.col.f32.bf16.bf16.f32 "
        "{%0,%1,%2,%3}, {%4,%5,%6,%7}, {%8,%9}, {%0,%1,%2,%3};"
        : "+f"(d[0]), "+f"(d[1]), "+f"(d[2]), "+f"(d[3])
        : "r"(a0), "r"(a1), "r"(a2), "r"(a3), "r"(b0), "r"(b1));
}

// pack bf16x2: x -> low half, y -> high half
__device__ __forceinline__ uint32_t pack_bf16(float x, float y) {
    uint32_t d;
    asm("cvt.rn.bf16x2.f32 %0, %1, %2;" : "=r"(d) : "f"(y), "f"(x));
    return d;
}
// Split fp32 pair into bf16 hi pack + bf16 residual pack (residual exact in fp32).
__device__ __forceinline__ void split_pair(float x, float y, uint32_t& h, uint32_t& l) {
    h = pack_bf16(x, y);
    float hx = __uint_as_float(h << 16);
    float hy = __uint_as_float(h & 0xFFFF0000u);
    l = pack_bf16(x - hx, y - hy);
}

__device__ __forceinline__ uint32_t smem_u32adr(const void* p) {
    uint32_t a;
    asm("{ .reg .u64 t; cvta.to.shared.u64 t, %1; cvt.u32.u64 %0, t; }" : "=r"(a) : "l"(p));
    return a;
}
__device__ __forceinline__ void cp16(uint32_t dst, const void* src) {
    asm volatile("cp.async.cg.shared.global [%0], [%1], 16;" :: "r"(dst), "l"(src));
}
#define CP_COMMIT()  asm volatile("cp.async.commit_group;" ::: "memory")
#define CP_WAIT(n)   asm volatile("cp.async.wait_group %0;" :: "n"(n) : "memory")

// Per CTA (256 thr): out[128,32] = W[idx[b]] @ x[b], 3xBF16-split m16n8k16.
// D = ah*bh + al*bh + ah*bl. Each of 8 warps owns 16 rows end-to-end with a
// private 3-stage cp.async ring (no CTA barriers in the loop). Halved warp
// tile doubles warps/SM at constant smem: 32 warps/SM resident (occ ~50%).
// A buffers pad-free XOR swizzle: phys = row*16 + ((slot^(row&3))<<2).
// B pre-split once as bf16 hi/lo packs. Index dtype resolved inline.
__global__ void __launch_bounds__(THREADS, 4) bmm_mma_kernel(
    const float* __restrict__ inp,
    const float* __restrict__ W,
    const int*   __restrict__ idx_raw,
    float* __restrict__ out)
{
    extern __shared__ char smem[];
    float*    As = (float*)smem;                 // per-warp: 3 stages x 256 floats
    uint32_t* Bs = (uint32_t*)(smem + A_BYTES);  // [32 n][132 u32]: hi(0..63) lo(64..127)

    const int blk = blockIdx.x;
    const int tid = threadIdx.x;
    const int wid = tid >> 5;
    const int lid = tid & 31;
    const int gid = lid >> 2;         // groupID 0..7
    const int tig = lid & 3;          // thread-in-group 0..3

    // ---- Inline index resolution: int64 (odd words all 0) vs int32 ----
    int odd = idx_raw[1] | idx_raw[3] | idx_raw[5] | idx_raw[7] | idx_raw[9];
    int g = odd ? idx_raw[blk] : idx_raw[2 * blk];
    g = (g < 0) ? 0 : ((g >= 1024) ? 1023 : g);

    // Warp-private A region; warp w owns gmem rows [16w, 16w+16).
    const float* Wg = W + (long long)g * (NBLK * NBLK) + (wid * 16) * NBLK;
    float* Aw = As + wid * (NSTAGE * AW_FLOATS);

    // One warp-chunk = 16 rows x 16 floats = 64 x 16B; 2 cp.async per lane.
    #define ISSUE_CHUNK(ck, buf) do {                                            \
        const float* srcb = Wg + (ck) * CHUNK_K;                                 \
        float* dstb = Aw + (buf) * AW_FLOATS;                                    \
        _Pragma("unroll")                                                        \
        for (int it = 0; it < 2; ++it) {                                         \
            int c = lid + 32 * it;                                               \
            int row = c >> 2, slot = c & 3;                                      \
            cp16(smem_u32adr(dstb + row * 16 + ((slot ^ (row & 3)) << 2)),       \
                 srcb + row * NBLK + slot * 4);                                  \
        }                                                                        \
        CP_COMMIT();                                                             \
    } while (0)

    ISSUE_CHUNK(0, 0);
    ISSUE_CHUNK(1, 1);

    // ---- Stage B pre-split: x[k][f] -> Bs[n][pair] bf16 hi/lo (256 thr, 2 its) ----
    {
        const float* xb = inp + (long long)blk * NBLK * FEAT;
        #pragma unroll
        for (int it = 0; it < 2; ++it) {
            int q  = tid + THREADS * it;       // 0..511
            int p  = q >> 3;                   // pair: k = 2p, 2p+1
            int nb = (q & 7) * 4;
            float4 v0 = *(const float4*)(xb + (2 * p)     * FEAT + nb);
            float4 v1 = *(const float4*)(xb + (2 * p + 1) * FEAT + nb);
            const float e0[4] = {v0.x, v0.y, v0.z, v0.w};
            const float e1[4] = {v1.x, v1.y, v1.z, v1.w};
            #pragma unroll
            for (int j = 0; j < 4; ++j) {
                uint32_t h, l;
                split_pair(e0[j], e1[j], h, l);
                Bs[(nb + j) * BSTRIDE_U32 + p]      = h;
                Bs[(nb + j) * BSTRIDE_U32 + 64 + p] = l;
            }
        }
    }
    __syncthreads();   // the ONLY CTA-wide barrier: B visible to all warps

    float d[4][4];
    #pragma unroll
    for (int nt = 0; nt < 4; ++nt)
        #pragma unroll
        for (int e = 0; e < 4; ++e) d[nt][e] = 0.0f;

    // Per-thread constant swizzled column offsets within the warp's 16-row block:
    const int acol_lo = (2 * tig) ^ ((gid & 3) << 2);   // cols 2tig, 2tig+1
    const int acol_hi = acol_lo ^ 8;                    // cols 2tig+8, 2tig+9
    // B fragment pointers: n = nt*8+gid, pairs (ck*8+tig) and (+4)
    const uint32_t* b_base = Bs + gid * BSTRIDE_U32 + tig;

    #pragma unroll
    for (int ck = 0; ck < NCHUNK; ++ck) {
        if (ck < NCHUNK - 1) { CP_WAIT(1); } else { CP_WAIT(0); }
        __syncwarp();     // cross-lane smem visibility within the warp

        if (ck + 2 < NCHUNK) ISSUE_CHUNK(ck + 2, (ck + 2) % NSTAGE);

        // ---- A fragments: swizzled float2 LDS, bf16 split (4 pairs) ----
        const float* p = Aw + (ck % NSTAGE) * AW_FLOATS + gid * 16;
        uint32_t ah[4], al[4];
        {
            float2 v0 = *(const float2*)(p + acol_lo);          // (r0,   k0,k0+1)
            float2 v1 = *(const float2*)(p + 128 + acol_lo);    // (r0+8, k0,k0+1)
            float2 v2 = *(const float2*)(p + acol_hi);          // (r0,   k0+8,+9)
            float2 v3 = *(const float2*)(p + 128 + acol_hi);    // (r0+8, k0+8,+9)
            split_pair(v0.x, v0.y, ah[0], al[0]);
            split_pair(v1.x, v1.y, ah[1], al[1]);
            split_pair(v2.x, v2.y, ah[2], al[2]);
            split_pair(v3.x, v3.y, ah[3], al[3]);
        }

        // ---- B fragments: direct LDS.32 of pre-split packs (conflict-free) ----
        uint32_t bh[4][2], bl[4][2];
        const int poff = ck * 8;
        #pragma unroll
        for (int nt = 0; nt < 4; ++nt) {
            const uint32_t* q = b_base + nt * 8 * BSTRIDE_U32 + poff;
            bh[nt][0] = q[0];
            bh[nt][1] = q[4];
            bl[nt][0] = q[64];
            bl[nt][1] = q[68];
        }

        // ---- Pass-major emission: hh, then al*bh, then ah*bl ----
        #pragma unroll
        for (int nt = 0; nt < 4; ++nt)
            mma_bf16(d[nt], ah[0], ah[1], ah[2], ah[3], bh[nt][0], bh[nt][1]);
        #pragma unroll
        for (int nt = 0; nt < 4; ++nt)
            mma_bf16(d[nt], al[0], al[1], al[2], al[3], bh[nt][0], bh[nt][1]);
        #pragma unroll
        for (int nt = 0; nt < 4; ++nt)
            mma_bf16(d[nt], ah[0], ah[1], ah[2], ah[3], bl[nt][0], bl[nt][1]);
    }

    // ---- Epilogue: write D fragments straight to gmem (float2 per pair) ----
    float* ob = out + (long long)blk * NBLK * FEAT;
    const int r0 = wid * 16 + gid;
    #pragma unroll
    for (int nt = 0; nt < 4; ++nt) {
        const int c = nt * 8 + tig * 2;
        *(float2*)(ob + r0 * FEAT + c)       = make_float2(d[nt][0], d[nt][1]);
        *(float2*)(ob + (r0 + 8) * FEAT + c) = make_float2(d[nt][2], d[nt][3]);
    }
}

extern "C" void kernel_launch(void* const* d_in, const int* in_sizes, int n_in,
                              void* d_out, int out_size) {
    // Select pointers by element count (robust to metadata ordering).
    const float* inp = nullptr;
    const float* W   = nullptr;
    const void*  idx = nullptr;
    for (int i = 0; i < n_in; ++i) {
        if      (in_sizes[i] == 4194304)  inp = (const float*)d_in[i];
        else if (in_sizes[i] == 16777216) W   = (const float*)d_in[i];
        else if (in_sizes[i] == 1024)     idx = d_in[i];
    }

    cudaFuncSetAttribute(bmm_mma_kernel, cudaFuncAttributeMaxDynamicSharedMemorySize,
                         SMEM_BYTES);
    bmm_mma_kernel<<<NBATCH, THREADS, SMEM_BYTES>>>(inp, W, (const int*)idx,
                                                    (float*)d_out);
}

// round 16
// speedup vs baseline: 1.0135x; 1.0135x over previous
#include <cuda_runtime.h>
#include <cstdint>

#define NBLK    128
#define FEAT    32
#define THREADS 128
#define NBATCH  1024

#define NCHUNK   8            // k-chunks of 16 (one m16n8k16 step each)
#define CHUNK_K  16
#define AW_FLOATS 512         // 32 rows x 16 floats, XOR-swizzled, NO pad
#define NSTAGE   3
#define A_BYTES  (4 * NSTAGE * AW_FLOATS * 4)   // 24576
#define BQ_STRIDE 36          // uint4 per B row (32 quads + 4 pad): LDS.128 conflict-free
#define B_BYTES  (32 * BQ_STRIDE * 16)          // 18432
#define SMEM_BYTES (A_BYTES + B_BYTES)          // 43008 -> 5 CTAs/SM

// m16n8k16 bf16 mma: D += A*B, fp32 accumulate.
__device__ __forceinline__ void mma_bf16(float* d, uint32_t a0, uint32_t a1,
                                         uint32_t a2, uint32_t a3,
                                         uint32_t b0, uint32_t b1) {
    asm("mma.sync.aligned.m16n8k16.row.col.f32.bf16.bf16.f32 "
        "{%0,%1,%2,%3}, {%4,%5,%6,%7}, {%8,%9}, {%0,%1,%2,%3};"
        : "+f"(d[0]), "+f"(d[1]), "+f"(d[2]), "+f"(d[3])
        : "r"(a0), "r"(a1), "r"(a2), "r"(a3), "r"(b0), "r"(b1));
}

// pack bf16x2: x -> low half, y -> high half
__device__ __forceinline__ uint32_t pack_bf16(float x, float y) {
    uint32_t d;
    asm("cvt.rn.bf16x2.f32 %0, %1, %2;" : "=r"(d) : "f"(y), "f"(x));
    return d;
}
// Split fp32 pair into bf16 hi pack + bf16 residual pack (residual exact in fp32).
__device__ __forceinline__ void split_pair(float x, float y, uint32_t& h, uint32_t& l) {
    h = pack_bf16(x, y);
    float hx = __uint_as_float(h << 16);
    float hy = __uint_as_float(h & 0xFFFF0000u);
    l = pack_bf16(x - hx, y - hy);
}

__device__ __forceinline__ uint32_t smem_u32adr(const void* p) {
    uint32_t a;
    asm("{ .reg .u64 t; cvta.to.shared.u64 t, %1; cvt.u32.u64 %0, t; }" : "=r"(a) : "l"(p));
    return a;
}
__device__ __forceinline__ void cp16(uint32_t dst, const void* src) {
    asm volatile("cp.async.cg.shared.global [%0], [%1], 16;" :: "r"(dst), "l"(src));
}
#define CP_COMMIT()  asm volatile("cp.async.commit_group;" ::: "memory")
#define CP_WAIT(n)   asm volatile("cp.async.wait_group %0;" :: "n"(n) : "memory")

// Per CTA: out[128,32] = W[idx[b]] @ x[b] via 3xBF16-split m16n8k16 mma.sync.
// D = ah*bh + al*bh + ah*bl. Warp-private 3-stage cp.async rings (no in-loop
// CTA barriers). A: pad-free XOR swizzle phys = row*16 + ((slot^(row&3))<<2).
// B: staged once as per-fragment QUADS {bh0,bh1,bl0,bl1} so each (nt,chunk)
// fragment is ONE LDS.128 (4 per chunk instead of 16 LDS.32); row stride 36
// quads keeps 8-lane phases conflict-free (36 = 4 mod 8 -> s mod 8 bijective).
// 43KB smem -> 5 CTAs/SM.
__global__ void __launch_bounds__(THREADS, 5) bmm_mma_kernel(
    const float* __restrict__ inp,
    const float* __restrict__ W,
    const int*   __restrict__ idx_raw,
    float* __restrict__ out)
{
    extern __shared__ char smem[];
    float* As = (float*)smem;                    // per-warp: 3 stages x 512 floats
    uint4* Bq = (uint4*)(smem + A_BYTES);        // [32 n][36 quads]
    uint32_t* Bw = (uint32_t*)Bq;                // word view for staging scatter

    const int blk = blockIdx.x;
    const int tid = threadIdx.x;
    const int wid = tid >> 5;
    const int lid = tid & 31;
    const int gid = lid >> 2;         // groupID 0..7
    const int tig = lid & 3;          // thread-in-group 0..3

    // ---- Inline index resolution: int64 (odd words all 0) vs int32 ----
    int odd = idx_raw[1] | idx_raw[3] | idx_raw[5] | idx_raw[7] | idx_raw[9];
    int g = odd ? idx_raw[blk] : idx_raw[2 * blk];
    g = (g < 0) ? 0 : ((g >= 1024) ? 1023 : g);

    // Warp-private A region and gmem row base (warp w owns rows [32w, 32w+32)).
    const float* Wg = W + (long long)g * (NBLK * NBLK) + (wid * 32) * NBLK;
    float* Aw = As + wid * (NSTAGE * AW_FLOATS);

    // One warp-chunk = 32 rows x 16 floats; 4 cp.async per lane, swizzled dst.
    #define ISSUE_CHUNK(ck, buf) do {                                            \
        const float* srcb = Wg + (ck) * CHUNK_K;                                 \
        float* dstb = Aw + (buf) * AW_FLOATS;                                    \
        _Pragma("unroll")                                                        \
        for (int it = 0; it < 4; ++it) {                                         \
            int c = lid + 32 * it;                                               \
            int row = c >> 2, slot = c & 3;                                      \
            cp16(smem_u32adr(dstb + row * 16 + ((slot ^ (row & 3)) << 2)),       \
                 srcb + row * NBLK + slot * 4);                                  \
        }                                                                        \
        CP_COMMIT();                                                             \
    } while (0)

    ISSUE_CHUNK(0, 0);
    ISSUE_CHUNK(1, 1);

    // ---- Stage B pre-split into quads: Bq[n][ck*4+tig] = {h(p), h(p+4), l(p), l(p+4)}
    // where p = ck*8 + tig. Thread handles pair p (k=2p,2p+1), n's nb..nb+3:
    // contributes h/l at quad slot (p&7)>>2 ? {1,3} : {0,2}.
    {
        const float* xb = inp + (long long)blk * NBLK * FEAT;
        #pragma unroll
        for (int it = 0; it < 4; ++it) {
            int q  = tid + THREADS * it;       // 0..511
            int p  = q >> 3;                   // pair index 0..63
            int nb = (q & 7) * 4;
            int ck = p >> 3;
            int r  = p & 7;
            int tg = r & 3;
            int sh = r >> 2;                   // 0 -> slots {0,2}, 1 -> slots {1,3}
            float4 v0 = *(const float4*)(xb + (2 * p)     * FEAT + nb);
            float4 v1 = *(const float4*)(xb + (2 * p + 1) * FEAT + nb);
            const float e0[4] = {v0.x, v0.y, v0.z, v0.w};
            const float e1[4] = {v1.x, v1.y, v1.z, v1.w};
            #pragma unroll
            for (int j = 0; j < 4; ++j) {
                uint32_t h, l;
                split_pair(e0[j], e1[j], h, l);
                uint32_t base = ((nb + j) * BQ_STRIDE + ck * 4 + tg) * 4;
                Bw[base + sh]     = h;
                Bw[base + 2 + sh] = l;
            }
        }
    }
    __syncthreads();   // the ONLY CTA-wide barrier: B visible to all warps

    float d[2][4][4];
    #pragma unroll
    for (int mt = 0; mt < 2; ++mt)
        #pragma unroll
        for (int nt = 0; nt < 4; ++nt)
            #pragma unroll
            for (int e = 0; e < 4; ++e) d[mt][nt][e] = 0.0f;

    // Per-thread constant swizzled column offsets within an A row block:
    const int acol_lo = (2 * tig) ^ ((gid & 3) << 2);   // cols 2tig,2tig+1
    const int acol_hi = acol_lo ^ 8;                    // cols 2tig+8,2tig+9
    // B quad base: n = nt*8+gid, quad = ck*4+tig
    const uint4* bq_base = Bq + gid * BQ_STRIDE + tig;

    #pragma unroll
    for (int ck = 0; ck < NCHUNK; ++ck) {
        if (ck < NCHUNK - 1) { CP_WAIT(1); } else { CP_WAIT(0); }
        __syncwarp();     // cross-lane smem visibility within the warp

        if (ck + 2 < NCHUNK) ISSUE_CHUNK(ck + 2, (ck + 2) % NSTAGE);

        // ---- A fragments: swizzled float2 LDS (2-phase min), bf16 split ----
        const float* a_stage = Aw + (ck % NSTAGE) * AW_FLOATS + gid * 16;
        uint32_t ah[2][4], al[2][4];
        #pragma unroll
        for (int mt = 0; mt < 2; ++mt) {
            const float* p = a_stage + mt * (16 * 16);          // +16 rows
            float2 v0 = *(const float2*)(p + acol_lo);          // (r0,   k0,k0+1)
            float2 v1 = *(const float2*)(p + 128 + acol_lo);    // (r0+8, k0,k0+1)
            float2 v2 = *(const float2*)(p + acol_hi);          // (r0,   k0+8,+9)
            float2 v3 = *(const float2*)(p + 128 + acol_hi);    // (r0+8, k0+8,+9)
            split_pair(v0.x, v0.y, ah[mt][0], al[mt][0]);
            split_pair(v1.x, v1.y, ah[mt][1], al[mt][1]);
            split_pair(v2.x, v2.y, ah[mt][2], al[mt][2]);
            split_pair(v3.x, v3.y, ah[mt][3], al[mt][3]);
        }

        // ---- B fragments: ONE LDS.128 per n-tile (conflict-free, stride 36) ----
        uint32_t bh[4][2], bl[4][2];
        #pragma unroll
        for (int nt = 0; nt < 4; ++nt) {
            uint4 v = bq_base[nt * 8 * BQ_STRIDE + ck * 4];
            bh[nt][0] = v.x; bh[nt][1] = v.y;
            bl[nt][0] = v.z; bl[nt][1] = v.w;
        }

        // ---- Pass-major emission: hh, then al*bh, then ah*bl ----
        #pragma unroll
        for (int mt = 0; mt < 2; ++mt)
            #pragma unroll
            for (int nt = 0; nt < 4; ++nt)
                mma_bf16(d[mt][nt], ah[mt][0], ah[mt][1], ah[mt][2], ah[mt][3],
                         bh[nt][0], bh[nt][1]);
        #pragma unroll
        for (int mt = 0; mt < 2; ++mt)
            #pragma unroll
            for (int nt = 0; nt < 4; ++nt)
                mma_bf16(d[mt][nt], al[mt][0], al[mt][1], al[mt][2], al[mt][3],
                         bh[nt][0], bh[nt][1]);
        #pragma unroll
        for (int mt = 0; mt < 2; ++mt)
            #pragma unroll
            for (int nt = 0; nt < 4; ++nt)
                mma_bf16(d[mt][nt], ah[mt][0], ah[mt][1], ah[mt][2], ah[mt][3],
                         bl[nt][0], bl[nt][1]);
    }

    // ---- Epilogue: write D fragments straight to gmem (float2 per pair) ----
    float* ob = out + (long long)blk * NBLK * FEAT;
    #pragma unroll
    for (int mt = 0; mt < 2; ++mt) {
        const int r0 = wid * 32 + mt * 16 + gid;
        #pragma unroll
        for (int nt = 0; nt < 4; ++nt) {
            const int c = nt * 8 + tig * 2;
            *(float2*)(ob + r0 * FEAT + c)       = make_float2(d[mt][nt][0], d[mt][nt][1]);
            *(float2*)(ob + (r0 + 8) * FEAT + c) = make_float2(d[mt][nt][2], d[mt][nt][3]);
        }
    }
}

extern "C" void kernel_launch(void* const* d_in, const int* in_sizes, int n_in,
                              void* d_out, int out_size) {
    // Select pointers by element count (robust to metadata ordering).
    const float* inp = nullptr;
    const float* W   = nullptr;
    const void*  idx = nullptr;
    for (int i = 0; i < n_in; ++i) {
        if      (in_sizes[i] == 4194304)  inp = (const float*)d_in[i];
        else if (in_sizes[i] == 16777216) W   = (const float*)d_in[i];
        else if (in_sizes[i] == 1024)     idx = d_in[i];
    }

    cudaFuncSetAttribute(bmm_mma_kernel, cudaFuncAttributeMaxDynamicSharedMemorySize,
                         SMEM_BYTES);
    bmm_mma_kernel<<<NBATCH, THREADS, SMEM_BYTES>>>(inp, W, (const int*)idx,
                                                    (float*)d_out);
}